// round 2
// baseline (speedup 1.0000x reference)
#include <cuda_runtime.h>
#include <cuda_bf16.h>
#include <cstdint>

#define N_NODES 10000
#define N_EDGES 320000
#define BITMAP_WORDS 3125000  // ceil(10000*10000/32)

// ---------------- scratch (static device globals; no allocation) ----------------
__device__ unsigned int g_bitmap[BITMAP_WORDS];
__device__ float g_deg[N_NODES];
__device__ float g_h1[N_NODES * 256];
__device__ float g_h2[N_NODES * 256];
__device__ float g_h3[N_NODES * 128];
__device__ float g_mean[256];
__device__ float g_rstd[256];
__device__ int g_is64;

// ---------------- dtype detection: int64 iff high words of first 64 values all zero ----------------
__global__ void detect_kernel(const unsigned int* __restrict__ w) {
    if (threadIdx.x == 0 && blockIdx.x == 0) {
        int is64 = 1;
#pragma unroll
        for (int i = 0; i < 64; i++) {
            if (w[2 * i + 1] != 0u) { is64 = 0; break; }
        }
        g_is64 = is64;
    }
}

// ---------------- init: zero bitmap, deg = 1 (the eye() diagonal) ----------------
__global__ void init_kernel() {
    int i = blockIdx.x * blockDim.x + threadIdx.x;
    if (i < BITMAP_WORDS) g_bitmap[i] = 0u;
    if (i < N_NODES) g_deg[i] = 1.0f;
}

// ---------------- degree with dedup (set semantics) ----------------
__global__ void deg_kernel(const void* __restrict__ ei_raw) {
    int e = blockIdx.x * blockDim.x + threadIdx.x;
    if (e >= N_EDGES) return;
    int s, d;
    if (g_is64) {
        const long long* p = (const long long*)ei_raw;
        s = (int)p[e];
        d = (int)p[e + N_EDGES];
    } else {
        const int* p = (const int*)ei_raw;
        s = p[e];
        d = p[e + N_EDGES];
    }
    if ((unsigned)s >= N_NODES || (unsigned)d >= N_NODES) return;  // safety: never OOB
    if (s == d) return;  // diagonal already 1 via eye()
    unsigned long long bit = (unsigned long long)s * N_NODES + (unsigned long long)d;
    unsigned int mask = 1u << ((unsigned)bit & 31u);
    unsigned int old = atomicOr(&g_bitmap[bit >> 5], mask);
    if (!(old & mask)) atomicAdd(&g_deg[s], 1.0f);  // exact & order-independent
}

// ---------------- fp32 tiled GEMM: C = relu( (rs ? diag(rs) : I) * A @ W + bias ) ----------------
#define BM 64
#define BN 64
#define BK 16

__global__ void gemm_bias_relu(const float* __restrict__ A, const float* __restrict__ rs,
                               const float* __restrict__ W, const float* __restrict__ bias,
                               float* __restrict__ C, int M, int K, int N) {
    __shared__ float As[BK][BM + 4];  // A tile transposed, padded (row stride 272B, 16B-aligned)
    __shared__ float Bs[BK][BN];

    int tid = threadIdx.x;           // 256 threads
    int tx = tid & 15, ty = tid >> 4;
    int row0 = blockIdx.y * BM;
    int col0 = blockIdx.x * BN;

    float acc[4][4] = {};

    for (int k0 = 0; k0 < K; k0 += BK) {
#pragma unroll
        for (int i = 0; i < 4; i++) {
            int idx = tid + i * 256;
            int r = idx / BK, c = idx % BK;
            int gr = row0 + r, gc = k0 + c;
            float v = 0.f;
            if (gr < M && gc < K) {
                v = A[(long long)gr * K + gc];
                if (rs) v *= rs[gr];
            }
            As[c][r] = v;
        }
#pragma unroll
        for (int i = 0; i < 4; i++) {
            int idx = tid + i * 256;
            int r = idx / BN, c = idx % BN;
            int gr = k0 + r, gc = col0 + c;
            Bs[r][c] = (gr < K && gc < N) ? W[(long long)gr * N + gc] : 0.f;
        }
        __syncthreads();
#pragma unroll
        for (int kk = 0; kk < BK; kk++) {
            float4 a4 = *(const float4*)&As[kk][ty * 4];
            float4 b4 = *(const float4*)&Bs[kk][tx * 4];
            float a[4] = {a4.x, a4.y, a4.z, a4.w};
            float b[4] = {b4.x, b4.y, b4.z, b4.w};
#pragma unroll
            for (int i = 0; i < 4; i++)
#pragma unroll
                for (int j = 0; j < 4; j++)
                    acc[i][j] = fmaf(a[i], b[j], acc[i][j]);
        }
        __syncthreads();
    }

#pragma unroll
    for (int i = 0; i < 4; i++) {
        int gr = row0 + ty * 4 + i;
        if (gr >= M) continue;
#pragma unroll
        for (int j = 0; j < 4; j++) {
            int gc = col0 + tx * 4 + j;
            if (gc >= N) continue;
            float v = acc[i][j] + bias[gc];
            C[(long long)gr * N + gc] = v > 0.f ? v : 0.f;
        }
    }
}

// ---------------- BatchNorm stats: per-column mean & rstd (biased var) ----------------
__global__ void bn_stats(const float* __restrict__ H, int M, int N) {
    int c = blockIdx.x * 32 + threadIdx.x;   // N multiple of 32
    float s = 0.f, s2 = 0.f;
    for (int r = threadIdx.y; r < M; r += 8) {
        float v = H[(long long)r * N + c];
        s += v;
        s2 += v * v;
    }
    __shared__ float sh[8][32], sh2[8][32];
    sh[threadIdx.y][threadIdx.x] = s;
    sh2[threadIdx.y][threadIdx.x] = s2;
    __syncthreads();
    if (threadIdx.y == 0) {
#pragma unroll
        for (int y = 1; y < 8; y++) { s += sh[y][threadIdx.x]; s2 += sh2[y][threadIdx.x]; }
        float m = s / (float)M;
        float var = s2 / (float)M - m * m;
        g_mean[c] = m;
        g_rstd[c] = rsqrtf(var + 1e-5f);
    }
}

// ---------------- BatchNorm apply (in place), optional row-scale fold for next conv ----------------
__global__ void bn_apply(float* __restrict__ H, const float* __restrict__ g,
                         const float* __restrict__ b, const float* __restrict__ rs,
                         int M, int N) {
    int idx = blockIdx.x * blockDim.x + threadIdx.x;
    if (idx >= M * N) return;
    int j = idx % N, i = idx / N;
    float v = (H[idx] - g_mean[j]) * g_rstd[j] * g[j] + b[j];
    if (rs) v *= rs[i];
    H[idx] = v;
}

// ---------------- launch ----------------
extern "C" void kernel_launch(void* const* d_in, const int* in_sizes, int n_in,
                              void* d_out, int out_size) {
    const float* x   = (const float*)d_in[0];
    const void*  ei  = d_in[1];                  // int32 or int64, detected on device
    const float* W0  = (const float*)d_in[2];
    const float* b0  = (const float*)d_in[3];
    const float* g0  = (const float*)d_in[4];
    const float* be0 = (const float*)d_in[5];
    const float* W1  = (const float*)d_in[6];
    const float* b1  = (const float*)d_in[7];
    const float* g1  = (const float*)d_in[8];
    const float* be1 = (const float*)d_in[9];
    const float* fW0 = (const float*)d_in[10];
    const float* fb0 = (const float*)d_in[11];
    const float* fW1 = (const float*)d_in[12];
    const float* fb1 = (const float*)d_in[13];
    float* out = (float*)d_out;

    float *deg, *h1, *h2, *h3;
    cudaGetSymbolAddress((void**)&deg, g_deg);
    cudaGetSymbolAddress((void**)&h1, g_h1);
    cudaGetSymbolAddress((void**)&h2, g_h2);
    cudaGetSymbolAddress((void**)&h3, g_h3);

    const int M = N_NODES;

    // degree
    detect_kernel<<<1, 32>>>((const unsigned int*)ei);
    init_kernel<<<(BITMAP_WORDS + 255) / 256, 256>>>();
    deg_kernel<<<(N_EDGES + 255) / 256, 256>>>(ei);

    // conv0: h1 = relu( (deg .* x) @ W0 + b0 ), then BN (fold deg for conv1 into apply)
    {
        dim3 grid(256 / BN, (M + BM - 1) / BM);
        gemm_bias_relu<<<grid, 256>>>(x, deg, W0, b0, h1, M, 500, 256);
        bn_stats<<<256 / 32, dim3(32, 8)>>>(h1, M, 256);
        bn_apply<<<(M * 256 + 255) / 256, 256>>>(h1, g0, be0, deg, M, 256);
    }
    // conv1: h2 = relu( h1 @ W1 + b1 )  (deg already folded), then BN
    {
        dim3 grid(256 / BN, (M + BM - 1) / BM);
        gemm_bias_relu<<<grid, 256>>>(h1, nullptr, W1, b1, h2, M, 256, 256);
        bn_stats<<<256 / 32, dim3(32, 8)>>>(h2, M, 256);
        bn_apply<<<(M * 256 + 255) / 256, 256>>>(h2, g1, be1, nullptr, M, 256);
    }
    // fc0: h3 = relu( h2 @ fW0 + fb0 )
    {
        dim3 grid(128 / BN, (M + BM - 1) / BM);
        gemm_bias_relu<<<grid, 256>>>(h2, nullptr, fW0, fb0, h3, M, 256, 128);
    }
    // fc1: out = relu( h3 @ fW1 + fb1 )   N=40 (guarded by BN tile)
    {
        dim3 grid(1, (M + BM - 1) / BM);
        gemm_bias_relu<<<grid, 256>>>(h3, nullptr, fW1, fb1, out, M, 128, 40);
    }
}

// round 3
// speedup vs baseline: 1.3034x; 1.3034x over previous
#include <cuda_runtime.h>
#include <cuda_bf16.h>
#include <cstdint>

#define N_NODES 10000
#define N_EDGES 320000
#define BITMAP_WORDS 3125000  // ceil(10000*10000/32)
#define MAX_BY 79             // ceil(10000/128)

// ---------------- scratch (static device globals; no allocation) ----------------
__device__ unsigned int g_bitmap[BITMAP_WORDS];
__device__ float g_deg[N_NODES];
__device__ float g_h1[N_NODES * 256];
__device__ float g_h2[N_NODES * 256];
__device__ float g_h3[N_NODES * 128];
__device__ float g_psum[MAX_BY * 256];
__device__ float g_psum2[MAX_BY * 256];
__device__ float g_mean[256];
__device__ float g_rstd[256];
__device__ int g_is64;

// ---------------- dtype detection: int64 iff high words of first 64 values all zero --------
__global__ void detect_kernel(const unsigned int* __restrict__ w) {
    if (threadIdx.x == 0 && blockIdx.x == 0) {
        int is64 = 1;
#pragma unroll
        for (int i = 0; i < 64; i++) {
            if (w[2 * i + 1] != 0u) { is64 = 0; break; }
        }
        g_is64 = is64;
    }
}

// ---------------- init: zero bitmap (vectorized), deg = 1 ----------------
__global__ void init_kernel() {
    int i = blockIdx.x * blockDim.x + threadIdx.x;
    if (i < BITMAP_WORDS / 4 + 1) {
        uint4 z = {0u, 0u, 0u, 0u};
        if (4 * i + 3 < BITMAP_WORDS) *(uint4*)&g_bitmap[4 * i] = z;
        else for (int j = 4 * i; j < BITMAP_WORDS; j++) g_bitmap[j] = 0u;
    }
    if (i < N_NODES) g_deg[i] = 1.0f;
}

// ---------------- degree with dedup (set semantics) ----------------
__global__ void deg_kernel(const void* __restrict__ ei_raw) {
    int e = blockIdx.x * blockDim.x + threadIdx.x;
    if (e >= N_EDGES) return;
    int s, d;
    if (g_is64) {
        const long long* p = (const long long*)ei_raw;
        s = (int)p[e];
        d = (int)p[e + N_EDGES];
    } else {
        const int* p = (const int*)ei_raw;
        s = p[e];
        d = p[e + N_EDGES];
    }
    if ((unsigned)s >= N_NODES || (unsigned)d >= N_NODES) return;
    if (s == d) return;  // diagonal already 1 via eye()
    unsigned long long bit = (unsigned long long)s * N_NODES + (unsigned long long)d;
    unsigned int mask = 1u << ((unsigned)bit & 31u);
    unsigned int old = atomicOr(&g_bitmap[bit >> 5], mask);
    if (!(old & mask)) atomicAdd(&g_deg[s], 1.0f);
}

// ---------------- tiled SGEMM, 8x8 microtile: C = relu(diag(rs?)*A @ W + bias) -------------
// Optionally emits per-(blockrow, column) partial sums/sumsq of the output (for BN stats).
template <int BM, int BN, bool STATS>
__global__ void __launch_bounds__((BM / 8) * (BN / 8), 2)
gemm_tile(const float* __restrict__ A, const float* __restrict__ rs,
          const float* __restrict__ W, const float* __restrict__ bias,
          float* __restrict__ C, int M, int K, int N,
          float* __restrict__ psum, float* __restrict__ psum2) {
    constexpr int TX = BN / 8;
    constexpr int TY = BM / 8;
    constexpr int THREADS = TX * TY;

    __shared__ float As[8][BM + 4];
    __shared__ float Bs[8][BN];
    __shared__ float shS[TY][BN];
    __shared__ float shS2[TY][BN];

    const int tid = threadIdx.x;
    const int tx = tid % TX, ty = tid / TX;
    const int row0 = blockIdx.y * BM;
    const int col0 = blockIdx.x * BN;

    float acc[8][8] = {};

    for (int k0 = 0; k0 < K; k0 += 8) {
        // load A tile (transposed into smem), folding row scale
#pragma unroll
        for (int idx = tid; idx < BM * 2; idx += THREADS) {
            int m = idx >> 1, q = idx & 1;
            int gr = row0 + m, gk = k0 + q * 4;
            float4 v = {0.f, 0.f, 0.f, 0.f};
            if (gr < M) {
                if (gk + 3 < K) {
                    v = *(const float4*)&A[(size_t)gr * K + gk];
                } else {
                    float t[4] = {0.f, 0.f, 0.f, 0.f};
                    for (int j = 0; j < 4; j++)
                        if (gk + j < K) t[j] = A[(size_t)gr * K + gk + j];
                    v = make_float4(t[0], t[1], t[2], t[3]);
                }
                if (rs) {
                    float r = rs[gr];
                    v.x *= r; v.y *= r; v.z *= r; v.w *= r;
                }
            }
            As[q * 4 + 0][m] = v.x;
            As[q * 4 + 1][m] = v.y;
            As[q * 4 + 2][m] = v.z;
            As[q * 4 + 3][m] = v.w;
        }
        // load B tile
#pragma unroll
        for (int idx = tid; idx < 8 * BN; idx += THREADS) {
            int k = idx / BN, n = idx % BN;
            int gk = k0 + k, gn = col0 + n;
            Bs[k][n] = (gk < K && gn < N) ? W[(size_t)gk * N + gn] : 0.f;
        }
        __syncthreads();
#pragma unroll
        for (int kk = 0; kk < 8; kk++) {
            float4 a0 = *(const float4*)&As[kk][ty * 8];
            float4 a1 = *(const float4*)&As[kk][ty * 8 + 4];
            float4 b0 = *(const float4*)&Bs[kk][tx * 8];
            float4 b1 = *(const float4*)&Bs[kk][tx * 8 + 4];
            float a[8] = {a0.x, a0.y, a0.z, a0.w, a1.x, a1.y, a1.z, a1.w};
            float b[8] = {b0.x, b0.y, b0.z, b0.w, b1.x, b1.y, b1.z, b1.w};
#pragma unroll
            for (int i = 0; i < 8; i++)
#pragma unroll
                for (int j = 0; j < 8; j++)
                    acc[i][j] = fmaf(a[i], b[j], acc[i][j]);
        }
        __syncthreads();
    }

    // epilogue: bias + relu + store (+ per-column partial stats)
    float cs[8] = {}, cs2[8] = {};
    float bj[8];
#pragma unroll
    for (int j = 0; j < 8; j++) {
        int gc = col0 + tx * 8 + j;
        bj[j] = (gc < N) ? bias[gc] : 0.f;
    }
#pragma unroll
    for (int i = 0; i < 8; i++) {
        int gr = row0 + ty * 8 + i;
        if (gr >= M) continue;
#pragma unroll
        for (int j = 0; j < 8; j++) {
            int gc = col0 + tx * 8 + j;
            if (gc >= N) continue;
            float v = acc[i][j] + bj[j];
            v = v > 0.f ? v : 0.f;
            C[(size_t)gr * N + gc] = v;
            if (STATS) { cs[j] += v; cs2[j] += v * v; }
        }
    }
    if (STATS) {
#pragma unroll
        for (int j = 0; j < 8; j++) {
            shS[ty][tx * 8 + j] = cs[j];
            shS2[ty][tx * 8 + j] = cs2[j];
        }
        __syncthreads();
        for (int c = tid; c < BN; c += THREADS) {
            int gc = col0 + c;
            if (gc >= N) continue;
            float s = 0.f, s2 = 0.f;
#pragma unroll
            for (int y = 0; y < TY; y++) { s += shS[y][c]; s2 += shS2[y][c]; }
            psum[blockIdx.y * N + gc] = s;
            psum2[blockIdx.y * N + gc] = s2;
        }
    }
}

// ---------------- BN finalize: mean/rstd from partial sums ----------------
__global__ void bn_finalize(int nby, int N, int M) {
    int c = blockIdx.x * blockDim.x + threadIdx.x;
    if (c >= N) return;
    float s = 0.f, s2 = 0.f;
    for (int b = 0; b < nby; b++) { s += g_psum[b * N + c]; s2 += g_psum2[b * N + c]; }
    float m = s / (float)M;
    float var = s2 / (float)M - m * m;
    g_mean[c] = m;
    g_rstd[c] = rsqrtf(var + 1e-5f);
}

// ---------------- BN apply (in place, vectorized), optional row-scale fold ----------------
__global__ void bn_apply(float* __restrict__ H, const float* __restrict__ g,
                         const float* __restrict__ b, const float* __restrict__ rs,
                         int M, int N) {
    int idx = blockIdx.x * blockDim.x + threadIdx.x;  // over M*N/4 float4s
    int n4 = N >> 2;
    if (idx >= M * n4) return;
    int row = idx / n4, c4 = (idx % n4) * 4;
    float4 h = *(float4*)&H[(size_t)row * N + c4];
    float r = rs ? rs[row] : 1.f;
    float* hp = &h.x;
#pragma unroll
    for (int j = 0; j < 4; j++) {
        int c = c4 + j;
        hp[j] = ((hp[j] - g_mean[c]) * g_rstd[c] * g[c] + b[c]) * r;
    }
    *(float4*)&H[(size_t)row * N + c4] = h;
}

// ---------------- launch ----------------
extern "C" void kernel_launch(void* const* d_in, const int* in_sizes, int n_in,
                              void* d_out, int out_size) {
    const float* x   = (const float*)d_in[0];
    const void*  ei  = d_in[1];
    const float* W0  = (const float*)d_in[2];
    const float* b0  = (const float*)d_in[3];
    const float* g0  = (const float*)d_in[4];
    const float* be0 = (const float*)d_in[5];
    const float* W1  = (const float*)d_in[6];
    const float* b1  = (const float*)d_in[7];
    const float* g1  = (const float*)d_in[8];
    const float* be1 = (const float*)d_in[9];
    const float* fW0 = (const float*)d_in[10];
    const float* fb0 = (const float*)d_in[11];
    const float* fW1 = (const float*)d_in[12];
    const float* fb1 = (const float*)d_in[13];
    float* out = (float*)d_out;

    float *deg, *h1, *h2, *h3, *ps, *ps2;
    cudaGetSymbolAddress((void**)&deg, g_deg);
    cudaGetSymbolAddress((void**)&h1, g_h1);
    cudaGetSymbolAddress((void**)&h2, g_h2);
    cudaGetSymbolAddress((void**)&h3, g_h3);
    cudaGetSymbolAddress((void**)&ps, g_psum);
    cudaGetSymbolAddress((void**)&ps2, g_psum2);

    const int M = N_NODES;
    const int NBY = MAX_BY;  // 79

    // degree
    detect_kernel<<<1, 32>>>((const unsigned int*)ei);
    init_kernel<<<(BITMAP_WORDS / 4 + 256) / 256, 256>>>();
    deg_kernel<<<(N_EDGES + 255) / 256, 256>>>(ei);

    // conv0: h1 = relu((deg.*x) @ W0 + b0); BN stats fused; BN apply folds deg for conv1
    gemm_tile<128, 128, true><<<dim3(2, NBY), 256>>>(x, deg, W0, b0, h1, M, 500, 256, ps, ps2);
    bn_finalize<<<1, 256>>>(NBY, 256, M);
    bn_apply<<<(M * 64 + 255) / 256, 256>>>(h1, g0, be0, deg, M, 256);

    // conv1: h2 = relu(h1 @ W1 + b1); BN stats fused
    gemm_tile<128, 128, true><<<dim3(2, NBY), 256>>>(h1, nullptr, W1, b1, h2, M, 256, 256, ps, ps2);
    bn_finalize<<<1, 256>>>(NBY, 256, M);
    bn_apply<<<(M * 64 + 255) / 256, 256>>>(h2, g1, be1, nullptr, M, 256);

    // fc0: h3 = relu(h2 @ fW0 + fb0)
    gemm_tile<128, 64, false><<<dim3(2, NBY), 128>>>(h2, nullptr, fW0, fb0, h3, M, 256, 128,
                                                     nullptr, nullptr);
    // fc1: out = relu(h3 @ fW1 + fb1), N=40 guarded
    gemm_tile<128, 64, false><<<dim3(1, NBY), 128>>>(h3, nullptr, fW1, fb1, out, M, 128, 40,
                                                     nullptr, nullptr);
}

// round 5
// speedup vs baseline: 1.9387x; 1.4874x over previous
#include <cuda_runtime.h>
#include <cuda_bf16.h>
#include <cstdint>

#define N_NODES 10000
#define N_EDGES 320000
#define BITMAP_WORDS 3125000  // ceil(10000*10000/32)

// ---------------- scratch (static device globals; no allocation) ----------------
__device__ unsigned int g_bitmap[BITMAP_WORDS];
__device__ float g_deg[N_NODES];
__device__ float g_h1[N_NODES * 256];
__device__ float g_h2[N_NODES * 256];
__device__ float g_h3[N_NODES * 128];
__device__ float g_psum[16 * 256];
__device__ float g_psum2[16 * 256];
__device__ float g_mean[256];
__device__ float g_rstd[256];
__device__ int g_is64;
// transposed + bf16-split weights, zero-padded: [Npad][KP]
__device__ __nv_bfloat16 g_wth0[256 * 512];
__device__ __nv_bfloat16 g_wtl0[256 * 512];
__device__ __nv_bfloat16 g_wth1[256 * 256];
__device__ __nv_bfloat16 g_wtl1[256 * 256];
__device__ __nv_bfloat16 g_wth2[128 * 256];
__device__ __nv_bfloat16 g_wtl2[128 * 256];
__device__ __nv_bfloat16 g_wth3[128 * 128];
__device__ __nv_bfloat16 g_wtl3[128 * 128];

// ---------------- helpers ----------------
__device__ __forceinline__ uint32_t s2u(const void* p) {
    uint32_t a;
    asm("{ .reg .u64 t; cvta.to.shared.u64 t, %1; cvt.u32.u64 %0, t; }" : "=r"(a) : "l"(p));
    return a;
}

__device__ __forceinline__ void bsplit(float v, unsigned short& h, unsigned short& l) {
    __nv_bfloat16 hb = __float2bfloat16(v);
    float r = v - __bfloat162float(hb);
    __nv_bfloat16 lb = __float2bfloat16(r);
    h = __bfloat16_as_ushort(hb);
    l = __bfloat16_as_ushort(lb);
}

#define LDX4(r, addr) \
    asm volatile("ldmatrix.sync.aligned.m8n8.x4.shared.b16 {%0,%1,%2,%3}, [%4];" \
                 : "=r"((r)[0]), "=r"((r)[1]), "=r"((r)[2]), "=r"((r)[3]) : "r"(addr))

#define MMA(d, a, b0, b1) \
    asm volatile("mma.sync.aligned.m16n8k16.row.col.f32.bf16.bf16.f32 " \
                 "{%0,%1,%2,%3}, {%4,%5,%6,%7}, {%8,%9}, {%0,%1,%2,%3};" \
                 : "+f"((d)[0]), "+f"((d)[1]), "+f"((d)[2]), "+f"((d)[3]) \
                 : "r"((a)[0]), "r"((a)[1]), "r"((a)[2]), "r"((a)[3]), "r"(b0), "r"(b1))

#define CP_ASYNC16(dst, src) \
    asm volatile("cp.async.cg.shared.global [%0], [%1], 16;" :: "r"(dst), "l"(src))

// ---------------- dtype detection (parallel) ----------------
__global__ void detect_kernel(const unsigned int* __restrict__ w) {
    unsigned t = threadIdx.x;
    unsigned bad = (w[2 * t + 1] != 0u) ? 1u : 0u;
    unsigned m = __ballot_sync(0xffffffffu, bad);
    if (t == 0) g_is64 = (m == 0) ? 1 : 0;
}

// ---------------- init: zero bitmap (vectorized), deg = 1 ----------------
__global__ void init_kernel() {
    int i = blockIdx.x * blockDim.x + threadIdx.x;
    if (i < BITMAP_WORDS / 4 + 1) {
        uint4 z = {0u, 0u, 0u, 0u};
        if (4 * i + 3 < BITMAP_WORDS) *(uint4*)&g_bitmap[4 * i] = z;
        else for (int j = 4 * i; j < BITMAP_WORDS; j++) g_bitmap[j] = 0u;
    }
    if (i < N_NODES) g_deg[i] = 1.0f;
}

// ---------------- degree with dedup (set semantics) ----------------
__global__ void deg_kernel(const void* __restrict__ ei_raw) {
    int e = blockIdx.x * blockDim.x + threadIdx.x;
    if (e >= N_EDGES) return;
    int s, d;
    if (g_is64) {
        const long long* p = (const long long*)ei_raw;
        s = (int)p[e];
        d = (int)p[e + N_EDGES];
    } else {
        const int* p = (const int*)ei_raw;
        s = p[e];
        d = p[e + N_EDGES];
    }
    if ((unsigned)s >= N_NODES || (unsigned)d >= N_NODES) return;
    if (s == d) return;  // diagonal already 1 via eye()
    unsigned long long bit = (unsigned long long)s * N_NODES + (unsigned long long)d;
    unsigned int mask = 1u << ((unsigned)bit & 31u);
    unsigned int old = atomicOr(&g_bitmap[bit >> 5], mask);
    if (!(old & mask)) atomicAdd(&g_deg[s], 1.0f);
}

// -------- weight transpose + bf16 split (zero-padded to [Npad][KP]) --------
__global__ void transpose_split(const float* __restrict__ W, __nv_bfloat16* __restrict__ th,
                                __nv_bfloat16* __restrict__ tl, int K, int KP, int N) {
    __shared__ float t[32][33];
    int k0 = blockIdx.x * 32, n0 = blockIdx.y * 32;
    for (int dy = threadIdx.y; dy < 32; dy += 8) {
        int k = k0 + dy, n = n0 + threadIdx.x;
        t[dy][threadIdx.x] = (k < K && n < N) ? W[(size_t)k * N + n] : 0.f;
    }
    __syncthreads();
    for (int dy = threadIdx.y; dy < 32; dy += 8) {
        int n = n0 + dy, k = k0 + threadIdx.x;
        float v = t[threadIdx.x][dy];
        unsigned short h, l;
        bsplit(v, h, l);
        th[(size_t)n * KP + k] = __ushort_as_bfloat16(h);
        tl[(size_t)n * KP + k] = __ushort_as_bfloat16(l);
    }
}

// ---------------- mma.sync bf16-split GEMM: C = relu(diag(rs?)*A @ W + bias) --------
// CTA 128x128, 8 warps (4x2) of 32x64 warp tiles, BK=32, double buffered.
#define ROWB 80
#define AH_OFF 0
#define AL_OFF 10240
#define BH_OFF 20480
#define BL_OFF 30720
#define BUF_SZ 40960
#define SMEM_DYN (2 * BUF_SZ + 1024)

__global__ void __launch_bounds__(256, 1)
gemm_mma(const float* __restrict__ A, const float* __restrict__ rs,
         const __nv_bfloat16* __restrict__ Wth, const __nv_bfloat16* __restrict__ Wtl,
         const float* __restrict__ bias, float* __restrict__ C,
         int M, int K, int KP, int Ncols) {
    extern __shared__ char smraw[];
    uint32_t raw = s2u(smraw);
    uint32_t sbase = (raw + 1023u) & ~1023u;
    char* sb = smraw + (sbase - raw);

    const int tid = threadIdx.x, lane = tid & 31, wid = tid >> 5;
    const int row0 = blockIdx.y * 128, col0 = blockIdx.x * 128;
    const int wm = (wid >> 1) * 32, wn = (wid & 1) * 64;
    const int nch = (K + 31) >> 5;

    float acc[2][8][4];
#pragma unroll
    for (int i = 0; i < 2; i++)
#pragma unroll
        for (int j = 0; j < 8; j++)
#pragma unroll
            for (int c = 0; c < 4; c++) acc[i][j][c] = 0.f;

    // ldmatrix per-lane address offsets
    const uint32_t a_lo = (uint32_t)((lane & 15) * ROWB + ((lane >> 4) & 1) * 16);
    const uint32_t b_lo = (uint32_t)((lane & 7) * ROWB + ((lane & 16) ? 8 * ROWB : 0) +
                                     ((lane & 8) ? 16 : 0));

    auto prefetch = [&](int ch) {
        const int k0 = ch << 5;
        const int buf = ch & 1;
        char* bufc = sb + buf * BUF_SZ;
        const uint32_t bufu = sbase + buf * BUF_SZ;
        // B tiles via cp.async (scratch is zero-padded; always in-bounds)
#pragma unroll
        for (int t = 0; t < 2; t++) {
            int idx = tid + t * 256;
            int n = idx >> 2, q = idx & 3;
            size_t so = (size_t)(col0 + n) * KP + k0 + q * 8;
            CP_ASYNC16(bufu + BH_OFF + n * ROWB + q * 16, (const void*)(Wth + so));
            CP_ASYNC16(bufu + BL_OFF + n * ROWB + q * 16, (const void*)(Wtl + so));
        }
        asm volatile("cp.async.commit_group;" ::: "memory");
        // A tile: fp32 -> bf16 hi/lo -> STS
        const bool fastk = (k0 + 32 <= K);
#pragma unroll
        for (int t = 0; t < 4; t++) {
            int idx = tid + t * 256;
            int r = idx >> 3, q = idx & 7;
            int gr = row0 + r, gk = k0 + q * 4;
            float v0 = 0.f, v1 = 0.f, v2 = 0.f, v3 = 0.f;
            if (gr < M) {
                if (fastk) {
                    float4 f = *(const float4*)&A[(size_t)gr * K + gk];
                    v0 = f.x; v1 = f.y; v2 = f.z; v3 = f.w;
                } else {
                    if (gk + 0 < K) v0 = A[(size_t)gr * K + gk + 0];
                    if (gk + 1 < K) v1 = A[(size_t)gr * K + gk + 1];
                    if (gk + 2 < K) v2 = A[(size_t)gr * K + gk + 2];
                    if (gk + 3 < K) v3 = A[(size_t)gr * K + gk + 3];
                }
                if (rs) { float s = rs[gr]; v0 *= s; v1 *= s; v2 *= s; v3 *= s; }
            }
            unsigned short h0, h1, h2, h3, l0, l1, l2, l3;
            bsplit(v0, h0, l0); bsplit(v1, h1, l1);
            bsplit(v2, h2, l2); bsplit(v3, h3, l3);
            *(uint2*)(bufc + AH_OFF + r * ROWB + q * 8) =
                make_uint2((uint32_t)h0 | ((uint32_t)h1 << 16),
                           (uint32_t)h2 | ((uint32_t)h3 << 16));
            *(uint2*)(bufc + AL_OFF + r * ROWB + q * 8) =
                make_uint2((uint32_t)l0 | ((uint32_t)l1 << 16),
                           (uint32_t)l2 | ((uint32_t)l3 << 16));
        }
    };

    for (int ch = 0; ch < nch; ch++) {
        if (ch == 0) prefetch(0);
        if (ch + 1 < nch) {
            prefetch(ch + 1);
            asm volatile("cp.async.wait_group 1;" ::: "memory");
        } else {
            asm volatile("cp.async.wait_group 0;" ::: "memory");
        }
        __syncthreads();

        const uint32_t bufu = sbase + (ch & 1) * BUF_SZ;
#pragma unroll
        for (int ks = 0; ks < 2; ks++) {
            uint32_t ka = bufu + AH_OFF + (uint32_t)(wm * ROWB) + a_lo + ks * 32;
            uint32_t ah0[4], ah1[4], al0[4], al1[4];
            LDX4(ah0, ka);
            LDX4(ah1, ka + 16 * ROWB);
            LDX4(al0, ka + (AL_OFF - AH_OFF));
            LDX4(al1, ka + (AL_OFF - AH_OFF) + 16 * ROWB);
#pragma unroll
            for (int nt = 0; nt < 4; nt++) {
                uint32_t kb = bufu + BH_OFF + (uint32_t)((wn + nt * 16) * ROWB) + b_lo + ks * 32;
                uint32_t bh[4], bl[4];
                LDX4(bh, kb);
                LDX4(bl, kb + (BL_OFF - BH_OFF));
                MMA(acc[0][nt * 2 + 0], ah0, bh[0], bh[1]);
                MMA(acc[1][nt * 2 + 0], ah1, bh[0], bh[1]);
                MMA(acc[0][nt * 2 + 1], ah0, bh[2], bh[3]);
                MMA(acc[1][nt * 2 + 1], ah1, bh[2], bh[3]);
                MMA(acc[0][nt * 2 + 0], al0, bh[0], bh[1]);
                MMA(acc[1][nt * 2 + 0], al1, bh[0], bh[1]);
                MMA(acc[0][nt * 2 + 1], al0, bh[2], bh[3]);
                MMA(acc[1][nt * 2 + 1], al1, bh[2], bh[3]);
                MMA(acc[0][nt * 2 + 0], ah0, bl[0], bl[1]);
                MMA(acc[1][nt * 2 + 0], ah1, bl[0], bl[1]);
                MMA(acc[0][nt * 2 + 1], ah0, bl[2], bl[3]);
                MMA(acc[1][nt * 2 + 1], ah1, bl[2], bl[3]);
            }
        }
        __syncthreads();
    }

    // epilogue: bias + relu, direct coalesced stores from fragments
#pragma unroll
    for (int mi = 0; mi < 2; mi++) {
        int r0_ = row0 + wm + mi * 16 + (lane >> 2);
#pragma unroll
        for (int n8 = 0; n8 < 8; n8++) {
            int gc = col0 + wn + n8 * 8 + (lane & 3) * 2;
            if (gc >= Ncols) continue;
            float bv0 = bias[gc], bv1 = bias[gc + 1];
            if (r0_ < M) {
                float v0 = acc[mi][n8][0] + bv0; v0 = v0 > 0.f ? v0 : 0.f;
                float v1 = acc[mi][n8][1] + bv1; v1 = v1 > 0.f ? v1 : 0.f;
                *(float2*)&C[(size_t)r0_ * Ncols + gc] = make_float2(v0, v1);
            }
            if (r0_ + 8 < M) {
                float v2 = acc[mi][n8][2] + bv0; v2 = v2 > 0.f ? v2 : 0.f;
                float v3 = acc[mi][n8][3] + bv1; v3 = v3 > 0.f ? v3 : 0.f;
                *(float2*)&C[(size_t)(r0_ + 8) * Ncols + gc] = make_float2(v2, v3);
            }
        }
    }
}

// ---------------- BN stats (parallel over 16 row blocks) ----------------
__global__ void bn_stats2(const float* __restrict__ H, int N) {
    int c = blockIdx.x * 32 + threadIdx.x;
    int rb = blockIdx.y;  // 16 blocks of 625 rows
    float s = 0.f, s2 = 0.f;
    for (int r = rb * 625 + threadIdx.y; r < rb * 625 + 625; r += 8) {
        float v = H[(size_t)r * N + c];
        s += v;
        s2 += v * v;
    }
    __shared__ float sh[8][32], sh2[8][32];
    sh[threadIdx.y][threadIdx.x] = s;
    sh2[threadIdx.y][threadIdx.x] = s2;
    __syncthreads();
    if (threadIdx.y == 0) {
#pragma unroll
        for (int y = 1; y < 8; y++) { s += sh[y][threadIdx.x]; s2 += sh2[y][threadIdx.x]; }
        g_psum[rb * N + c] = s;
        g_psum2[rb * N + c] = s2;
    }
}

__global__ void bn_finalize(int nrb, int N, int M) {
    int c = blockIdx.x * blockDim.x + threadIdx.x;
    if (c >= N) return;
    float s = 0.f, s2 = 0.f;
    for (int b = 0; b < nrb; b++) { s += g_psum[b * N + c]; s2 += g_psum2[b * N + c]; }
    float m = s / (float)M;
    float var = s2 / (float)M - m * m;
    g_mean[c] = m;
    g_rstd[c] = rsqrtf(var + 1e-5f);
}

__global__ void bn_apply(float* __restrict__ H, const float* __restrict__ g,
                         const float* __restrict__ b, const float* __restrict__ rs,
                         int M, int N) {
    int idx = blockIdx.x * blockDim.x + threadIdx.x;
    int n4 = N >> 2;
    if (idx >= M * n4) return;
    int row = idx / n4, c4 = (idx % n4) * 4;
    float4 h = *(float4*)&H[(size_t)row * N + c4];
    float r = rs ? rs[row] : 1.f;
    float* hp = &h.x;
#pragma unroll
    for (int j = 0; j < 4; j++) {
        int c = c4 + j;
        hp[j] = ((hp[j] - g_mean[c]) * g_rstd[c] * g[c] + b[c]) * r;
    }
    *(float4*)&H[(size_t)row * N + c4] = h;
}

// ---------------- launch ----------------
extern "C" void kernel_launch(void* const* d_in, const int* in_sizes, int n_in,
                              void* d_out, int out_size) {
    const float* x   = (const float*)d_in[0];
    const void*  ei  = d_in[1];
    const float* W0  = (const float*)d_in[2];
    const float* b0  = (const float*)d_in[3];
    const float* g0  = (const float*)d_in[4];
    const float* be0 = (const float*)d_in[5];
    const float* W1  = (const float*)d_in[6];
    const float* b1  = (const float*)d_in[7];
    const float* g1  = (const float*)d_in[8];
    const float* be1 = (const float*)d_in[9];
    const float* fW0 = (const float*)d_in[10];
    const float* fb0 = (const float*)d_in[11];
    const float* fW1 = (const float*)d_in[12];
    const float* fb1 = (const float*)d_in[13];
    float* out = (float*)d_out;

    float *deg, *h1, *h2, *h3;
    __nv_bfloat16 *wth0, *wtl0, *wth1, *wtl1, *wth2, *wtl2, *wth3, *wtl3;
    cudaGetSymbolAddress((void**)&deg, g_deg);
    cudaGetSymbolAddress((void**)&h1, g_h1);
    cudaGetSymbolAddress((void**)&h2, g_h2);
    cudaGetSymbolAddress((void**)&h3, g_h3);
    cudaGetSymbolAddress((void**)&wth0, g_wth0);
    cudaGetSymbolAddress((void**)&wtl0, g_wtl0);
    cudaGetSymbolAddress((void**)&wth1, g_wth1);
    cudaGetSymbolAddress((void**)&wtl1, g_wtl1);
    cudaGetSymbolAddress((void**)&wth2, g_wth2);
    cudaGetSymbolAddress((void**)&wtl2, g_wtl2);
    cudaGetSymbolAddress((void**)&wth3, g_wth3);
    cudaGetSymbolAddress((void**)&wtl3, g_wtl3);

    cudaFuncSetAttribute(gemm_mma, cudaFuncAttributeMaxDynamicSharedMemorySize, SMEM_DYN);

    const int M = N_NODES;
    dim3 tb(32, 8);

    // weight prep (zero-padded scratch)
    transpose_split<<<dim3(16, 8), tb>>>(W0, wth0, wtl0, 500, 512, 256);
    transpose_split<<<dim3(8, 8), tb>>>(W1, wth1, wtl1, 256, 256, 256);
    transpose_split<<<dim3(8, 4), tb>>>(fW0, wth2, wtl2, 256, 256, 128);
    transpose_split<<<dim3(4, 4), tb>>>(fW1, wth3, wtl3, 128, 128, 40);

    // degree
    detect_kernel<<<1, 32>>>((const unsigned int*)ei);
    init_kernel<<<(BITMAP_WORDS / 4 + 256) / 256, 256>>>();
    deg_kernel<<<(N_EDGES + 255) / 256, 256>>>(ei);

    // conv0: h1 = relu((deg.*x) @ W0 + b0); BN; fold deg for conv1 into apply
    gemm_mma<<<dim3(2, 79), 256, SMEM_DYN>>>(x, deg, wth0, wtl0, b0, h1, M, 500, 512, 256);
    bn_stats2<<<dim3(8, 16), tb>>>(h1, 256);
    bn_finalize<<<1, 256>>>(16, 256, M);
    bn_apply<<<(M * 64 + 255) / 256, 256>>>(h1, g0, be0, deg, M, 256);

    // conv1: h2 = relu(h1 @ W1 + b1); BN
    gemm_mma<<<dim3(2, 79), 256, SMEM_DYN>>>(h1, nullptr, wth1, wtl1, b1, h2, M, 256, 256, 256);
    bn_stats2<<<dim3(8, 16), tb>>>(h2, 256);
    bn_finalize<<<1, 256>>>(16, 256, M);
    bn_apply<<<(M * 64 + 255) / 256, 256>>>(h2, g1, be1, nullptr, M, 256);

    // fc0: h3 = relu(h2 @ fW0 + fb0)
    gemm_mma<<<dim3(1, 79), 256, SMEM_DYN>>>(h2, nullptr, wth2, wtl2, fb0, h3, M, 256, 256, 128);
    // fc1: out = relu(h3 @ fW1 + fb1)
    gemm_mma<<<dim3(1, 79), 256, SMEM_DYN>>>(h3, nullptr, wth3, wtl3, fb1, out, M, 128, 128, 40);
}

// round 6
// speedup vs baseline: 2.4896x; 1.2841x over previous
#include <cuda_runtime.h>
#include <cuda_bf16.h>
#include <cstdint>

#define N_NODES 10000
#define N_EDGES 320000
#define M_PAD 10112           // 79 * 128
#define BITMAP_WORDS 3125000  // ceil(10000*10000/32)

// ---------------- scratch (static device globals; no allocation) ----------------
__device__ unsigned int g_bitmap[BITMAP_WORDS];
__device__ float g_deg[N_NODES];
__device__ float g_h1[N_NODES * 256];
__device__ float g_h2[N_NODES * 256];
__device__ float g_psum[16 * 256];
__device__ float g_psum2[16 * 256];
__device__ float g_mean[256];
__device__ float g_rstd[256];
__device__ int g_is64;
// bf16-split activations, zero-padded rows to M_PAD
__device__ __nv_bfloat16 g_xh[M_PAD * 512];
__device__ __nv_bfloat16 g_xl[M_PAD * 512];
__device__ __nv_bfloat16 g_a1h[M_PAD * 256];
__device__ __nv_bfloat16 g_a1l[M_PAD * 256];
__device__ __nv_bfloat16 g_a2h[M_PAD * 256];
__device__ __nv_bfloat16 g_a2l[M_PAD * 256];
__device__ __nv_bfloat16 g_a3h[M_PAD * 128];
__device__ __nv_bfloat16 g_a3l[M_PAD * 128];
// transposed + bf16-split weights, zero-padded: [Npad][KP]
__device__ __nv_bfloat16 g_wth0[256 * 512];
__device__ __nv_bfloat16 g_wtl0[256 * 512];
__device__ __nv_bfloat16 g_wth1[256 * 256];
__device__ __nv_bfloat16 g_wtl1[256 * 256];
__device__ __nv_bfloat16 g_wth2[128 * 256];
__device__ __nv_bfloat16 g_wtl2[128 * 256];
__device__ __nv_bfloat16 g_wth3[128 * 128];
__device__ __nv_bfloat16 g_wtl3[128 * 128];

// ---------------- helpers ----------------
__device__ __forceinline__ uint32_t s2u(const void* p) {
    uint32_t a;
    asm("{ .reg .u64 t; cvta.to.shared.u64 t, %1; cvt.u32.u64 %0, t; }" : "=r"(a) : "l"(p));
    return a;
}

__device__ __forceinline__ void bsplit(float v, unsigned short& h, unsigned short& l) {
    __nv_bfloat16 hb = __float2bfloat16(v);
    float r = v - __bfloat162float(hb);
    __nv_bfloat16 lb = __float2bfloat16(r);
    h = __bfloat16_as_ushort(hb);
    l = __bfloat16_as_ushort(lb);
}

#define LDX4(r, addr) \
    asm volatile("ldmatrix.sync.aligned.m8n8.x4.shared.b16 {%0,%1,%2,%3}, [%4];" \
                 : "=r"((r)[0]), "=r"((r)[1]), "=r"((r)[2]), "=r"((r)[3]) : "r"(addr))

#define MMA(d, a, b0, b1) \
    asm volatile("mma.sync.aligned.m16n8k16.row.col.f32.bf16.bf16.f32 " \
                 "{%0,%1,%2,%3}, {%4,%5,%6,%7}, {%8,%9}, {%0,%1,%2,%3};" \
                 : "+f"((d)[0]), "+f"((d)[1]), "+f"((d)[2]), "+f"((d)[3]) \
                 : "r"((a)[0]), "r"((a)[1]), "r"((a)[2]), "r"((a)[3]), "r"(b0), "r"(b1))

#define CP_ASYNC16(dst, src) \
    asm volatile("cp.async.cg.shared.global [%0], [%1], 16;" :: "r"(dst), "l"(src))

// ---------------- dtype detection (parallel) ----------------
__global__ void detect_kernel(const unsigned int* __restrict__ w) {
    unsigned t = threadIdx.x;
    unsigned bad = (w[2 * t + 1] != 0u) ? 1u : 0u;
    unsigned m = __ballot_sync(0xffffffffu, bad);
    if (t == 0) g_is64 = (m == 0) ? 1 : 0;
}

// ---------------- init: zero bitmap (vectorized), deg = 1 ----------------
__global__ void init_kernel() {
    int i = blockIdx.x * blockDim.x + threadIdx.x;
    if (i < BITMAP_WORDS / 4 + 1) {
        uint4 z = {0u, 0u, 0u, 0u};
        if (4 * i + 3 < BITMAP_WORDS) *(uint4*)&g_bitmap[4 * i] = z;
        else for (int j = 4 * i; j < BITMAP_WORDS; j++) g_bitmap[j] = 0u;
    }
    if (i < N_NODES) g_deg[i] = 1.0f;
}

// ---------------- degree with dedup (set semantics) ----------------
__global__ void deg_kernel(const void* __restrict__ ei_raw) {
    int e = blockIdx.x * blockDim.x + threadIdx.x;
    if (e >= N_EDGES) return;
    int s, d;
    if (g_is64) {
        const long long* p = (const long long*)ei_raw;
        s = (int)p[e];
        d = (int)p[e + N_EDGES];
    } else {
        const int* p = (const int*)ei_raw;
        s = p[e];
        d = p[e + N_EDGES];
    }
    if ((unsigned)s >= N_NODES || (unsigned)d >= N_NODES) return;
    if (s == d) return;  // diagonal already 1 via eye()
    unsigned long long bit = (unsigned long long)s * N_NODES + (unsigned long long)d;
    unsigned int mask = 1u << ((unsigned)bit & 31u);
    unsigned int old = atomicOr(&g_bitmap[bit >> 5], mask);
    if (!(old & mask)) atomicAdd(&g_deg[s], 1.0f);
}

// -------- merged weight transpose + bf16 split (4 segments, one launch) --------
struct TSeg {
    const float* W;
    __nv_bfloat16 *th, *tl;
    int K, KP, N, Npad;
};

__global__ void transpose_split4(TSeg s0, TSeg s1, TSeg s2, TSeg s3) {
    TSeg s = (blockIdx.z == 0) ? s0 : (blockIdx.z == 1) ? s1 : (blockIdx.z == 2) ? s2 : s3;
    int k0 = blockIdx.x * 32, n0 = blockIdx.y * 32;
    if (k0 >= s.KP || n0 >= s.Npad) return;
    __shared__ float t[32][33];
    for (int dy = threadIdx.y; dy < 32; dy += 8) {
        int k = k0 + dy, n = n0 + threadIdx.x;
        t[dy][threadIdx.x] = (k < s.K && n < s.N) ? s.W[(size_t)k * s.N + n] : 0.f;
    }
    __syncthreads();
    for (int dy = threadIdx.y; dy < 32; dy += 8) {
        int n = n0 + dy, k = k0 + threadIdx.x;
        if (n < s.Npad && k < s.KP) {
            unsigned short h, l;
            bsplit(t[threadIdx.x][dy], h, l);
            s.th[(size_t)n * s.KP + k] = __ushort_as_bfloat16(h);
            s.tl[(size_t)n * s.KP + k] = __ushort_as_bfloat16(l);
        }
    }
}

// -------- split fp32 activation (optional row scale) into bf16 hi/lo, K zero-padded ----
__global__ void split_scale(const float* __restrict__ X, const float* __restrict__ rs,
                            __nv_bfloat16* __restrict__ oh, __nv_bfloat16* __restrict__ ol,
                            int M, int K, int KP) {
    int idx = blockIdx.x * blockDim.x + threadIdx.x;
    int n4 = KP >> 2;
    if (idx >= M * n4) return;
    int row = idx / n4, c4 = (idx % n4) * 4;
    float v[4] = {0.f, 0.f, 0.f, 0.f};
    if (c4 + 3 < K) {
        float4 f = *(const float4*)&X[(size_t)row * K + c4];
        v[0] = f.x; v[1] = f.y; v[2] = f.z; v[3] = f.w;
    } else {
#pragma unroll
        for (int j = 0; j < 4; j++)
            if (c4 + j < K) v[j] = X[(size_t)row * K + c4 + j];
    }
    float r = rs ? rs[row] : 1.f;
    unsigned short h[4], l[4];
#pragma unroll
    for (int j = 0; j < 4; j++) bsplit(v[j] * r, h[j], l[j]);
    *(uint2*)&oh[(size_t)row * KP + c4] =
        make_uint2((uint32_t)h[0] | ((uint32_t)h[1] << 16), (uint32_t)h[2] | ((uint32_t)h[3] << 16));
    *(uint2*)&ol[(size_t)row * KP + c4] =
        make_uint2((uint32_t)l[0] | ((uint32_t)l[1] << 16), (uint32_t)l[2] | ((uint32_t)l[3] << 16));
}

// ---------------- mma.sync bf16-split GEMM, full cp.async 3-stage pipeline ----------------
// CTA 128x128, 8 warps (4x2) of 32x64 warp tiles, BK=32.
// OUTM 0: fp32 C [M][Ncols] (guarded). OUTM 2: bf16 hi/lo split out [M_PAD][Ncols].
#define ROWB 80
#define AH_OFF 0
#define AL_OFF 10240
#define BH_OFF 20480
#define BL_OFF 30720
#define BUF_SZ 40960
#define STAGES 3
#define SMEM_DYN (STAGES * BUF_SZ + 1024)

template <int OUTM>
__global__ void __launch_bounds__(256, 1)
gemm_mma(const __nv_bfloat16* __restrict__ Ah, const __nv_bfloat16* __restrict__ Al,
         const __nv_bfloat16* __restrict__ Bh, const __nv_bfloat16* __restrict__ Bl,
         const float* __restrict__ bias, float* __restrict__ Cf,
         __nv_bfloat16* __restrict__ Ch, __nv_bfloat16* __restrict__ Cl,
         int M, int Kpad, int Ncols) {
    extern __shared__ char smraw[];
    uint32_t raw = s2u(smraw);
    uint32_t sbase = (raw + 1023u) & ~1023u;

    const int tid = threadIdx.x, lane = tid & 31, wid = tid >> 5;
    const int row0 = blockIdx.y * 128, col0 = blockIdx.x * 128;
    const int wm = (wid >> 1) * 32, wn = (wid & 1) * 64;
    const int nch = Kpad >> 5;

    float acc[2][8][4];
#pragma unroll
    for (int i = 0; i < 2; i++)
#pragma unroll
        for (int j = 0; j < 8; j++)
#pragma unroll
            for (int c = 0; c < 4; c++) acc[i][j][c] = 0.f;

    const uint32_t a_lo = (uint32_t)((lane & 15) * ROWB + ((lane >> 4) & 1) * 16);
    const uint32_t b_lo = (uint32_t)((lane & 7) * ROWB + ((lane & 16) ? 8 * ROWB : 0) +
                                     ((lane & 8) ? 16 : 0));

    auto prefetch = [&](int ch) {
        const int buf = ch % STAGES;
        const uint32_t bu = sbase + buf * BUF_SZ;
        const int k0 = ch << 5;
#pragma unroll
        for (int t = 0; t < 2; t++) {
            int idx = tid + t * 256;      // 0..511
            int r = idx >> 2, q = idx & 3;
            size_t ao = (size_t)(row0 + r) * Kpad + k0 + q * 8;
            size_t bo = (size_t)(col0 + r) * Kpad + k0 + q * 8;
            uint32_t so = (uint32_t)(r * ROWB + q * 16);
            CP_ASYNC16(bu + AH_OFF + so, (const void*)(Ah + ao));
            CP_ASYNC16(bu + AL_OFF + so, (const void*)(Al + ao));
            CP_ASYNC16(bu + BH_OFF + so, (const void*)(Bh + bo));
            CP_ASYNC16(bu + BL_OFF + so, (const void*)(Bl + bo));
        }
        asm volatile("cp.async.commit_group;" ::: "memory");
    };

    prefetch(0);
    prefetch(1);

    for (int ch = 0; ch < nch; ch++) {
        asm volatile("cp.async.wait_group 1;" ::: "memory");
        __syncthreads();
        if (ch + 2 < nch) prefetch(ch + 2);

        const uint32_t bufu = sbase + (ch % STAGES) * BUF_SZ;
#pragma unroll
        for (int ks = 0; ks < 2; ks++) {
            uint32_t ka = bufu + AH_OFF + (uint32_t)(wm * ROWB) + a_lo + ks * 32;
            uint32_t ah0[4], ah1[4], al0[4], al1[4];
            LDX4(ah0, ka);
            LDX4(ah1, ka + 16 * ROWB);
            LDX4(al0, ka + (AL_OFF - AH_OFF));
            LDX4(al1, ka + (AL_OFF - AH_OFF) + 16 * ROWB);
#pragma unroll
            for (int nt = 0; nt < 4; nt++) {
                uint32_t kb = bufu + BH_OFF + (uint32_t)((wn + nt * 16) * ROWB) + b_lo + ks * 32;
                uint32_t bh[4], bl[4];
                LDX4(bh, kb);
                LDX4(bl, kb + (BL_OFF - BH_OFF));
                MMA(acc[0][nt * 2 + 0], ah0, bh[0], bh[1]);
                MMA(acc[1][nt * 2 + 0], ah1, bh[0], bh[1]);
                MMA(acc[0][nt * 2 + 1], ah0, bh[2], bh[3]);
                MMA(acc[1][nt * 2 + 1], ah1, bh[2], bh[3]);
                MMA(acc[0][nt * 2 + 0], al0, bh[0], bh[1]);
                MMA(acc[1][nt * 2 + 0], al1, bh[0], bh[1]);
                MMA(acc[0][nt * 2 + 1], al0, bh[2], bh[3]);
                MMA(acc[1][nt * 2 + 1], al1, bh[2], bh[3]);
                MMA(acc[0][nt * 2 + 0], ah0, bl[0], bl[1]);
                MMA(acc[1][nt * 2 + 0], ah1, bl[0], bl[1]);
                MMA(acc[0][nt * 2 + 1], ah0, bl[2], bl[3]);
                MMA(acc[1][nt * 2 + 1], ah1, bl[2], bl[3]);
            }
        }
        __syncthreads();
    }

    // epilogue: bias + relu, direct coalesced stores from fragments
#pragma unroll
    for (int mi = 0; mi < 2; mi++) {
        int r0_ = row0 + wm + mi * 16 + (lane >> 2);
#pragma unroll
        for (int n8 = 0; n8 < 8; n8++) {
            int gc = col0 + wn + n8 * 8 + (lane & 3) * 2;
            if (gc >= Ncols) continue;
            float bv0 = bias[gc], bv1 = bias[gc + 1];
            float v0 = acc[mi][n8][0] + bv0; v0 = v0 > 0.f ? v0 : 0.f;
            float v1 = acc[mi][n8][1] + bv1; v1 = v1 > 0.f ? v1 : 0.f;
            float v2 = acc[mi][n8][2] + bv0; v2 = v2 > 0.f ? v2 : 0.f;
            float v3 = acc[mi][n8][3] + bv1; v3 = v3 > 0.f ? v3 : 0.f;
            if (OUTM == 0) {
                if (r0_ < M) *(float2*)&Cf[(size_t)r0_ * Ncols + gc] = make_float2(v0, v1);
                if (r0_ + 8 < M) *(float2*)&Cf[(size_t)(r0_ + 8) * Ncols + gc] = make_float2(v2, v3);
            } else {
                unsigned short h0, h1, h2, h3, l0, l1, l2, l3;
                bsplit(v0, h0, l0); bsplit(v1, h1, l1);
                bsplit(v2, h2, l2); bsplit(v3, h3, l3);
                if (r0_ < M) {
                    *(uint32_t*)&Ch[(size_t)r0_ * Ncols + gc] = (uint32_t)h0 | ((uint32_t)h1 << 16);
                    *(uint32_t*)&Cl[(size_t)r0_ * Ncols + gc] = (uint32_t)l0 | ((uint32_t)l1 << 16);
                }
                if (r0_ + 8 < M) {
                    *(uint32_t*)&Ch[(size_t)(r0_ + 8) * Ncols + gc] = (uint32_t)h2 | ((uint32_t)h3 << 16);
                    *(uint32_t*)&Cl[(size_t)(r0_ + 8) * Ncols + gc] = (uint32_t)l2 | ((uint32_t)l3 << 16);
                }
            }
        }
    }
}

// ---------------- BN stats (parallel over 16 row blocks) ----------------
__global__ void bn_stats2(const float* __restrict__ H, int N) {
    int c = blockIdx.x * 32 + threadIdx.x;
    int rb = blockIdx.y;  // 16 blocks of 625 rows
    float s = 0.f, s2 = 0.f;
    for (int r = rb * 625 + threadIdx.y; r < rb * 625 + 625; r += 8) {
        float v = H[(size_t)r * N + c];
        s += v;
        s2 += v * v;
    }
    __shared__ float sh[8][32], sh2[8][32];
    sh[threadIdx.y][threadIdx.x] = s;
    sh2[threadIdx.y][threadIdx.x] = s2;
    __syncthreads();
    if (threadIdx.y == 0) {
#pragma unroll
        for (int y = 1; y < 8; y++) { s += sh[y][threadIdx.x]; s2 += sh2[y][threadIdx.x]; }
        g_psum[rb * N + c] = s;
        g_psum2[rb * N + c] = s2;
    }
}

__global__ void bn_finalize(int nrb, int N, int M) {
    int c = blockIdx.x * blockDim.x + threadIdx.x;
    if (c >= N) return;
    float s = 0.f, s2 = 0.f;
    for (int b = 0; b < nrb; b++) { s += g_psum[b * N + c]; s2 += g_psum2[b * N + c]; }
    float m = s / (float)M;
    float var = s2 / (float)M - m * m;
    g_mean[c] = m;
    g_rstd[c] = rsqrtf(var + 1e-5f);
}

// -------- BN apply: fp32 in -> bf16 hi/lo split out (optional row-scale fold) --------
__global__ void bn_apply_split(const float* __restrict__ H, const float* __restrict__ g,
                               const float* __restrict__ b, const float* __restrict__ rs,
                               __nv_bfloat16* __restrict__ oh, __nv_bfloat16* __restrict__ ol,
                               int M, int N) {
    int idx = blockIdx.x * blockDim.x + threadIdx.x;
    int n4 = N >> 2;
    if (idx >= M * n4) return;
    int row = idx / n4, c4 = (idx % n4) * 4;
    float4 h = *(const float4*)&H[(size_t)row * N + c4];
    float r = rs ? rs[row] : 1.f;
    float* hp = &h.x;
    unsigned short hh[4], ll[4];
#pragma unroll
    for (int j = 0; j < 4; j++) {
        int c = c4 + j;
        float v = ((hp[j] - g_mean[c]) * g_rstd[c] * g[c] + b[c]) * r;
        bsplit(v, hh[j], ll[j]);
    }
    *(uint2*)&oh[(size_t)row * N + c4] =
        make_uint2((uint32_t)hh[0] | ((uint32_t)hh[1] << 16), (uint32_t)hh[2] | ((uint32_t)hh[3] << 16));
    *(uint2*)&ol[(size_t)row * N + c4] =
        make_uint2((uint32_t)ll[0] | ((uint32_t)ll[1] << 16), (uint32_t)ll[2] | ((uint32_t)ll[3] << 16));
}

// ---------------- launch ----------------
extern "C" void kernel_launch(void* const* d_in, const int* in_sizes, int n_in,
                              void* d_out, int out_size) {
    const float* x   = (const float*)d_in[0];
    const void*  ei  = d_in[1];
    const float* W0  = (const float*)d_in[2];
    const float* b0  = (const float*)d_in[3];
    const float* g0  = (const float*)d_in[4];
    const float* be0 = (const float*)d_in[5];
    const float* W1  = (const float*)d_in[6];
    const float* b1  = (const float*)d_in[7];
    const float* g1  = (const float*)d_in[8];
    const float* be1 = (const float*)d_in[9];
    const float* fW0 = (const float*)d_in[10];
    const float* fb0 = (const float*)d_in[11];
    const float* fW1 = (const float*)d_in[12];
    const float* fb1 = (const float*)d_in[13];
    float* out = (float*)d_out;

    float *deg, *h1, *h2;
    __nv_bfloat16 *xh, *xl, *a1h, *a1l, *a2h, *a2l, *a3h, *a3l;
    __nv_bfloat16 *wth0, *wtl0, *wth1, *wtl1, *wth2, *wtl2, *wth3, *wtl3;
    cudaGetSymbolAddress((void**)&deg, g_deg);
    cudaGetSymbolAddress((void**)&h1, g_h1);
    cudaGetSymbolAddress((void**)&h2, g_h2);
    cudaGetSymbolAddress((void**)&xh, g_xh);
    cudaGetSymbolAddress((void**)&xl, g_xl);
    cudaGetSymbolAddress((void**)&a1h, g_a1h);
    cudaGetSymbolAddress((void**)&a1l, g_a1l);
    cudaGetSymbolAddress((void**)&a2h, g_a2h);
    cudaGetSymbolAddress((void**)&a2l, g_a2l);
    cudaGetSymbolAddress((void**)&a3h, g_a3h);
    cudaGetSymbolAddress((void**)&a3l, g_a3l);
    cudaGetSymbolAddress((void**)&wth0, g_wth0);
    cudaGetSymbolAddress((void**)&wtl0, g_wtl0);
    cudaGetSymbolAddress((void**)&wth1, g_wth1);
    cudaGetSymbolAddress((void**)&wtl1, g_wtl1);
    cudaGetSymbolAddress((void**)&wth2, g_wth2);
    cudaGetSymbolAddress((void**)&wtl2, g_wtl2);
    cudaGetSymbolAddress((void**)&wth3, g_wth3);
    cudaGetSymbolAddress((void**)&wtl3, g_wtl3);

    cudaFuncSetAttribute(gemm_mma<0>, cudaFuncAttributeMaxDynamicSharedMemorySize, SMEM_DYN);
    cudaFuncSetAttribute(gemm_mma<2>, cudaFuncAttributeMaxDynamicSharedMemorySize, SMEM_DYN);

    const int M = N_NODES;
    dim3 tb(32, 8);

    // merged weight prep (one launch)
    TSeg s0 = {W0, wth0, wtl0, 500, 512, 256, 256};
    TSeg s1 = {W1, wth1, wtl1, 256, 256, 256, 256};
    TSeg s2 = {fW0, wth2, wtl2, 256, 256, 128, 128};
    TSeg s3 = {fW1, wth3, wtl3, 128, 128, 40, 128};
    transpose_split4<<<dim3(16, 8, 4), tb>>>(s0, s1, s2, s3);

    // degree
    detect_kernel<<<1, 32>>>((const unsigned int*)ei);
    init_kernel<<<(BITMAP_WORDS / 4 + 256) / 256, 256>>>();
    deg_kernel<<<(N_EDGES + 255) / 256, 256>>>(ei);

    // conv0 input: split (deg .* x) -> xh/xl  (Kpad 512)
    split_scale<<<(M * 128 + 255) / 256, 256>>>(x, deg, xh, xl, M, 500, 512);
    gemm_mma<0><<<dim3(2, 79), 256, SMEM_DYN>>>(xh, xl, wth0, wtl0, b0, h1, nullptr, nullptr,
                                                M, 512, 256);
    bn_stats2<<<dim3(8, 16), tb>>>(h1, 256);
    bn_finalize<<<1, 256>>>(16, 256, M);
    bn_apply_split<<<(M * 64 + 255) / 256, 256>>>(h1, g0, be0, deg, a1h, a1l, M, 256);

    // conv1
    gemm_mma<0><<<dim3(2, 79), 256, SMEM_DYN>>>(a1h, a1l, wth1, wtl1, b1, h2, nullptr, nullptr,
                                                M, 256, 256);
    bn_stats2<<<dim3(8, 16), tb>>>(h2, 256);
    bn_finalize<<<1, 256>>>(16, 256, M);
    bn_apply_split<<<(M * 64 + 255) / 256, 256>>>(h2, g1, be1, nullptr, a2h, a2l, M, 256);

    // fc0: split bf16 output directly for fc1
    gemm_mma<2><<<dim3(1, 79), 256, SMEM_DYN>>>(a2h, a2l, wth2, wtl2, fb0, nullptr, a3h, a3l,
                                                M, 256, 128);
    // fc1: fp32 out [10000][40]
    gemm_mma<0><<<dim3(1, 79), 256, SMEM_DYN>>>(a3h, a3l, wth3, wtl3, fb1, out, nullptr, nullptr,
                                                M, 128, 40);
}